// round 8
// baseline (speedup 1.0000x reference)
#include <cuda_runtime.h>
#include <cuda_fp16.h>
#include <cstdint>

#define CIN   672
#define COUT  128
#define HW    49
#define BTOT  1024
#define NTOT  (BTOT*HW)      // 50176
#define KC    32
#define NKC   21
#define STAGES 4

// ---- device scratch (allocation-free workaround) ----
__device__ __half H_buf[(size_t)CIN * NTOT];   // [c][b*49+s]  (K-major for GEMM B)
__device__ __half W16_buf[COUT * CIN];         // [o][c]

// ===================== K0: W -> fp16 =====================
__global__ void w_cvt_kernel(const float* __restrict__ W) {
    int i = blockIdx.x * 1024 + threadIdx.x;   // 84*1024 = 86016 exactly
    W16_buf[i] = __float2half(W[i]);
}

// ===================== K1: BN+ReLU+cvt stream =====================
__global__ void __launch_bounds__(512)
bn_kernel(const float* __restrict__ x,
          const float* __restrict__ gamma,
          const float* __restrict__ beta,
          const float* __restrict__ rmean,
          const float* __restrict__ rvar)
{
    __shared__ float2 ss[CIN];
    const int tid = threadIdx.x;
    for (int c = tid; c < CIN; c += 512) {
        float inv = rsqrtf(rvar[c] + 1e-5f);
        float s = gamma[c] * inv;
        ss[c] = make_float2(s, beta[c] - rmean[c] * s);
    }
    __syncthreads();

    const int b = blockIdx.x;
    const float4* xb = (const float4*)(x + (size_t)b * (CIN * HW));
    const int nb = b * HW;

    // 672*49 = 32928 floats = 8232 float4 per image
    #pragma unroll 4
    for (int it = 0; it < 17; it++) {
        int idx = tid + it * 512;
        if (idx < 8232) {
            float4 v = xb[idx];
            int i = idx * 4;
            #pragma unroll
            for (int e = 0; e < 4; e++) {
                int ii = i + e;
                int c = ii / 49;
                int s = ii - 49 * c;
                float2 sc = ss[c];
                float ve = (e == 0) ? v.x : (e == 1) ? v.y : (e == 2) ? v.z : v.w;
                float h = fmaxf(fmaf(ve, sc.x, sc.y), 0.0f);
                H_buf[(size_t)c * NTOT + nb + s] = __float2half(h);
            }
        }
    }
}

// ===================== K2: fp16 GEMM =====================
// C[128, 50176] = W16[128,672] @ H[672, 50176]; out reshaped [b][o][s]
#define NCTA2   128
#define GRID2   (NTOT / NCTA2)      // 392
#define STG_B   16384               // A 8KB + B 8KB per stage
#define B_OFF   8192
#define PS2     136                 // epilogue payload stride (words), conflict-free
#define SMEM2   (COUT * PS2 * 4)    // 69632 >= 4*16384

__device__ __forceinline__ void hmma16816(float c[4],
    uint32_t a0, uint32_t a1, uint32_t a2, uint32_t a3, uint32_t b0, uint32_t b1)
{
    asm volatile(
        "mma.sync.aligned.m16n8k16.row.col.f32.f16.f16.f32 "
        "{%0,%1,%2,%3}, {%4,%5,%6,%7}, {%8,%9}, {%0,%1,%2,%3};"
        : "+f"(c[0]), "+f"(c[1]), "+f"(c[2]), "+f"(c[3])
        : "r"(a0), "r"(a1), "r"(a2), "r"(a3), "r"(b0), "r"(b1));
}
__device__ __forceinline__ void ldsm_x4(uint32_t& r0, uint32_t& r1,
                                        uint32_t& r2, uint32_t& r3, uint32_t addr)
{
    asm volatile("ldmatrix.sync.aligned.m8n8.x4.shared.b16 {%0,%1,%2,%3}, [%4];"
                 : "=r"(r0), "=r"(r1), "=r"(r2), "=r"(r3) : "r"(addr));
}
__device__ __forceinline__ void ldsm_x4t(uint32_t& r0, uint32_t& r1,
                                         uint32_t& r2, uint32_t& r3, uint32_t addr)
{
    asm volatile("ldmatrix.sync.aligned.m8n8.x4.trans.shared.b16 {%0,%1,%2,%3}, [%4];"
                 : "=r"(r0), "=r"(r1), "=r"(r2), "=r"(r3) : "r"(addr));
}
__device__ __forceinline__ void cp16(uint32_t dst, const void* src) {
    asm volatile("cp.async.cg.shared.global [%0], [%1], 16;" :: "r"(dst), "l"(src) : "memory");
}
__device__ __forceinline__ uint32_t smem_u32(const void* p) {
    uint32_t a;
    asm("{ .reg .u64 t; cvta.to.shared.u64 t, %1; cvt.u32.u64 %0, t; }" : "=r"(a) : "l"(p));
    return a;
}

extern __shared__ char sm2[];

__global__ void __launch_bounds__(256, 2)
gemm_kernel(float* __restrict__ out)
{
    const int tid  = threadIdx.x;
    const int wid  = tid >> 5;
    const int lane = tid & 31;
    const int N0   = blockIdx.x * NCTA2;
    const uint32_t sb = smem_u32(sm2);

    // ---- per-thread cp.async offsets ----
    // A: 512 quads = 128 m x 4 q ; B: 512 quads = 32 k x 16 q
    const __half* a_src[2];
    const __half* b_src[2];
    uint32_t a_dst[2], b_dst[2];
    #pragma unroll
    for (int i = 0; i < 2; i++) {
        int ia = tid + i * 256;
        int m = ia >> 2, qa = ia & 3;
        a_src[i] = W16_buf + m * CIN + qa * 8;
        a_dst[i] = m * 64 + ((qa ^ ((m >> 1) & 3)) << 4);
        int k = ia >> 4, qb = ia & 15;
        b_src[i] = H_buf + (size_t)k * NTOT + N0 + qb * 8;
        b_dst[i] = B_OFF + k * 256 + ((qb ^ (k & 7)) << 4);
    }

    // ---- prologue: issue stages 0..2 ----
    #pragma unroll
    for (int st = 0; st < 3; st++) {
        uint32_t base = sb + st * STG_B;
        #pragma unroll
        for (int i = 0; i < 2; i++) {
            cp16(base + a_dst[i], a_src[i] + st * KC);
            cp16(base + b_dst[i], b_src[i] + (size_t)st * KC * NTOT);
        }
        asm volatile("cp.async.commit_group;" ::: "memory");
    }

    // ---- warp tiling: 4 M-warps x 2 N-warps ----
    const int m0w = (wid & 3) * 32;
    const int n0w = (wid >> 2) * 64;
    const int lrow = lane & 15;
    const int lqk  = (lane >> 4) & 1;
    const int asw  = (lrow >> 1) & 3;     // A swizzle (lane const)
    const int ksw  = lane & 7;            // B swizzle (lane const)

    float acc[2][8][4];
    #pragma unroll
    for (int mt = 0; mt < 2; mt++)
        #pragma unroll
        for (int nt = 0; nt < 8; nt++)
            #pragma unroll
            for (int i = 0; i < 4; i++) acc[mt][nt][i] = 0.0f;

    #pragma unroll 1
    for (int kc = 0; kc < NKC; kc++) {
        asm volatile("cp.async.wait_group 2;" ::: "memory");
        __syncthreads();

        const uint32_t Ab = sb + (kc & 3) * STG_B;
        const uint32_t Bb = Ab + B_OFF;

        #pragma unroll
        for (int ks = 0; ks < 2; ks++) {
            uint32_t a[2][4];
            const int qa = ks * 2 + lqk;
            #pragma unroll
            for (int mt = 0; mt < 2; mt++) {
                int mrow = m0w + mt * 16 + lrow;
                ldsm_x4(a[mt][0], a[mt][1], a[mt][2], a[mt][3],
                        Ab + mrow * 64 + ((qa ^ asw) << 4));
            }
            uint32_t b[8][2];
            const int krow = ks * 16 + lrow;
            const uint32_t brow_base = Bb + krow * 256;
            #pragma unroll
            for (int np = 0; np < 4; np++) {
                int q = (n0w >> 3) + np * 2 + lqk;
                ldsm_x4t(b[2*np][0], b[2*np][1], b[2*np+1][0], b[2*np+1][1],
                         brow_base + ((q ^ ksw) << 4));
            }
            #pragma unroll
            for (int nt = 0; nt < 8; nt++) {
                hmma16816(acc[0][nt], a[0][0], a[0][1], a[0][2], a[0][3], b[nt][0], b[nt][1]);
                hmma16816(acc[1][nt], a[1][0], a[1][1], a[1][2], a[1][3], b[nt][0], b[nt][1]);
            }
        }

        // issue stage kc+3
        const int kcn = kc + 3;
        if (kcn < NKC) {
            uint32_t base = sb + (kcn & 3) * STG_B;
            #pragma unroll
            for (int i = 0; i < 2; i++) {
                cp16(base + a_dst[i], a_src[i] + kcn * KC);
                cp16(base + b_dst[i], b_src[i] + (size_t)kcn * KC * NTOT);
            }
        }
        asm volatile("cp.async.commit_group;" ::: "memory");
    }

    // ---- epilogue: acc -> P[o][nl] -> out[b][o][s] ----
    __syncthreads();
    float* P = (float*)sm2;
    const int g = lane >> 2, t = lane & 3;
    #pragma unroll
    for (int mt = 0; mt < 2; mt++) {
        const int rb = m0w + mt * 16 + g;
        #pragma unroll
        for (int nt = 0; nt < 8; nt++) {
            const int cb = n0w + nt * 8 + 2 * t;
            *(float2*)&P[rb * PS2 + cb]       = make_float2(acc[mt][nt][0], acc[mt][nt][1]);
            *(float2*)&P[(rb + 8) * PS2 + cb] = make_float2(acc[mt][nt][2], acc[mt][nt][3]);
        }
    }
    __syncthreads();

    #pragma unroll 8
    for (int it = 0; it < 64; it++) {
        int f = tid + it * 256;          // 16384 = 128o x 128n
        int o = f >> 7, nl = f & 127;
        int ng = N0 + nl;
        int b = ng / 49;
        int s = ng - 49 * b;
        out[(size_t)b * (COUT * HW) + o * HW + s] = P[o * PS2 + nl];
    }
}

extern "C" void kernel_launch(void* const* d_in, const int* in_sizes, int n_in,
                              void* d_out, int out_size)
{
    const float* x     = (const float*)d_in[0];
    const float* gamma = (const float*)d_in[1];
    const float* beta  = (const float*)d_in[2];
    const float* rmean = (const float*)d_in[3];
    const float* rvar  = (const float*)d_in[4];
    const float* W     = (const float*)d_in[5];
    float* out = (float*)d_out;

    w_cvt_kernel<<<84, 1024>>>(W);
    bn_kernel<<<BTOT, 512>>>(x, gamma, beta, rmean, rvar);
    cudaFuncSetAttribute(gemm_kernel,
                         cudaFuncAttributeMaxDynamicSharedMemorySize, SMEM2);
    gemm_kernel<<<GRID2, 256, SMEM2>>>(out);
}

// round 9
// speedup vs baseline: 1.4374x; 1.4374x over previous
#include <cuda_runtime.h>
#include <cuda_fp16.h>
#include <cstdint>

#define CIN   672
#define COUT  128
#define HW    49
#define NB    2
#define NREAL 98          // NB*HW
#define NPAD  112
#define KC    32
#define NKC   21
#define GRID  512

#define LDA 20            // A row stride (half2 words): conflict-free frag reads
#define LDB 24            // B row stride (half2 words)
#define A_WORDS (COUT*LDA)   // 2560
#define B_WORDS (NPAD*LDB)   // 2688

#define OFF_SS 0                         // float2[672] = 1344 words
#define OFF_A0 1344
#define OFF_A1 (OFF_A0 + A_WORDS)
#define OFF_B0 (OFF_A1 + A_WORDS)
#define OFF_B1 (OFF_B0 + B_WORDS)
#define PIPE_WORDS (OFF_B1 + B_WORDS)    // 11840 words
#define PS 113
#define P_WORDS (COUT*PS)                // 14464 words
#define SMEM_WORDS (P_WORDS > PIPE_WORDS ? P_WORDS : PIPE_WORDS)
#define SMEM_BYTES (SMEM_WORDS*4)        // 57856 -> 2 CTAs/SM

// ---- fp16 copy of W, produced once by K0 ----
__device__ __align__(16) __half W16_buf[COUT * CIN];

__global__ void w_cvt_kernel(const float* __restrict__ W) {
    int i = blockIdx.x * 256 + threadIdx.x;      // 84*256 = 21504 = 86016/4
    float4 v = *(const float4*)(W + i * 4);
    __half2 h0 = __floats2half2_rn(v.x, v.y);
    __half2 h1 = __floats2half2_rn(v.z, v.w);
    uint2 q;
    q.x = *(uint32_t*)&h0;
    q.y = *(uint32_t*)&h1;
    *(uint2*)(W16_buf + i * 4) = q;
}

__device__ __forceinline__ void hmma16816(float c[4],
    uint32_t a0, uint32_t a1, uint32_t a2, uint32_t a3, uint32_t b0, uint32_t b1)
{
    asm volatile(
        "mma.sync.aligned.m16n8k16.row.col.f32.f16.f16.f32 "
        "{%0,%1,%2,%3}, {%4,%5,%6,%7}, {%8,%9}, {%0,%1,%2,%3};"
        : "+f"(c[0]), "+f"(c[1]), "+f"(c[2]), "+f"(c[3])
        : "r"(a0), "r"(a1), "r"(a2), "r"(a3), "r"(b0), "r"(b1));
}
__device__ __forceinline__ uint32_t pack_h2(float lo, float hi) {
    __half2 h = __floats2half2_rn(lo, hi);
    return *reinterpret_cast<uint32_t*>(&h);
}
__device__ __forceinline__ uint32_t smem_u32(const void* p) {
    uint32_t a;
    asm("{ .reg .u64 t; cvta.to.shared.u64 t, %1; cvt.u32.u64 %0, t; }" : "=r"(a) : "l"(p));
    return a;
}
__device__ __forceinline__ void cp16(uint32_t dst, const void* src) {
    asm volatile("cp.async.cg.shared.global [%0], [%1], 16;" :: "r"(dst), "l"(src) : "memory");
}

extern __shared__ uint32_t sm[];

__global__ void __launch_bounds__(256, 2)
bn_conv_f16c(const float* __restrict__ x,
             const float* __restrict__ gamma,
             const float* __restrict__ beta,
             const float* __restrict__ rmean,
             const float* __restrict__ rvar,
             float* __restrict__ out)
{
    const int tid  = threadIdx.x;
    const int wid  = tid >> 5;
    const int lane = tid & 31;
    const int g = lane >> 2, t = lane & 3;
    const int m0 = (wid & 3) * 32;        // 4 warps over M=128
    const int n0 = (wid >> 2) * 56;       // 2 warps over N=112
    const uint32_t sb = smem_u32(sm);

    float2* ssc = (float2*)(sm + OFF_SS);
    const float* sscf = (const float*)ssc;

    // ---- prologue: BN fold + zero B buffers ----
    for (int c = tid; c < CIN; c += 256) {
        float inv = rsqrtf(rvar[c] + 1e-5f);
        float s = gamma[c] * inv;
        ssc[c] = make_float2(s, beta[c] - rmean[c] * s);
    }
    for (int i = tid; i < 2 * B_WORDS; i += 256) sm[OFF_B0 + i] = 0u;

    // ---- per-thread staging constants ----
    // B: 784 pair-slots = 8 p x 98 n ; lane-consecutive n (coalesced LDG)
    int xoff[4], bsts[4], klr[4];
    #pragma unroll
    for (int j = 0; j < 4; j++) {
        int i = tid + j * 256;
        if (i > 783) i = 783;
        int p = i / 98;
        int n = i - 98 * p;
        int tp = p & 3, ks = p >> 2;
        int kl = ks * 16 + tp * 2;
        int b = (n >= HW) ? 1 : 0;
        int s = n - HW * b;
        xoff[j] = (b * CIN + kl) * HW + s;
        bsts[j] = n * LDB + 2 * ((p + ((n >> 2) & 7)) & 7);   // conflict-free STS swizzle
        klr[j]  = kl;
    }
    const bool v3 = (tid < 16);

    // A cp.async: 512 quads = 128 m x 4 q, 2 per thread
    const __half* a_src[2];
    uint32_t a_dw[2];                 // word offset within A buffer
    #pragma unroll
    for (int i = 0; i < 2; i++) {
        int ia = tid + i * 256;
        int m = ia >> 2, q = ia & 3;
        a_src[i] = W16_buf + m * CIN + q * 8;
        a_dw[i]  = m * LDA + q * 4;
    }

    const float* xb = x + (size_t)blockIdx.x * NB * CIN * HW;
    __syncthreads();

    float acc[2][7][4];
    #pragma unroll
    for (int mt = 0; mt < 2; mt++)
        #pragma unroll
        for (int nt = 0; nt < 7; nt++)
            #pragma unroll
            for (int i = 0; i < 4; i++) acc[mt][nt][i] = 0.0f;

    const int ar00 = (m0 + g) * LDA;
    const int ar01 = (m0 + g + 8) * LDA;
    const int ar10 = (m0 + 16 + g) * LDA;
    const int ar11 = (m0 + 24 + g) * LDA;
    const int bnb  = (n0 + g) * LDB;
    const int csl  = (n0 >> 2) + (g >> 2);   // reader swizzle base: (n>>2) = n0/4 + 2nt + (g>>2)

    float xv[4][4];

    #pragma unroll 1
    for (int kc = -1; kc < NKC; kc++) {
        const int kcn = kc + 1;

        // ---- issue cp.async A(kcn) into the free buffer ----
        if (kcn < NKC) {
            const uint32_t abase = sb + ((kcn & 1) ? OFF_A1 : OFF_A0) * 4;
            #pragma unroll
            for (int i = 0; i < 2; i++)
                cp16(abase + a_dw[i] * 4, a_src[i] + kcn * KC);
        }
        asm volatile("cp.async.commit_group;" ::: "memory");

        // ---- issue x LDGs for chunk kcn ----
        if (kcn < NKC) {
            const int xadd = kcn * (KC * HW);
            #pragma unroll
            for (int j = 0; j < 4; j++) {
                if (j < 3 || v3) {
                    const float* px = xb + xoff[j] + xadd;
                    xv[j][0] = px[0];
                    xv[j][1] = px[HW];
                    xv[j][2] = px[8 * HW];
                    xv[j][3] = px[9 * HW];
                }
            }
        }

        // ---- MMA on chunk kc ----
        if (kc >= 0) {
            const uint32_t* As = sm + ((kc & 1) ? OFF_A1 : OFF_A0);
            const uint32_t* Bs = sm + ((kc & 1) ? OFF_B1 : OFF_B0);
            #pragma unroll
            for (int ks = 0; ks < 2; ks++) {
                const int ka = ks * 8 + t;
                uint32_t a0[4], a1[4];
                a0[0] = As[ar00 + ka];     a0[1] = As[ar01 + ka];
                a0[2] = As[ar00 + ka + 4]; a0[3] = As[ar01 + ka + 4];
                a1[0] = As[ar10 + ka];     a1[1] = As[ar11 + ka];
                a1[2] = As[ar10 + ka + 4]; a1[3] = As[ar11 + ka + 4];
                const int pr = ks * 4 + t;
                #pragma unroll
                for (int nt = 0; nt < 7; nt++) {
                    const int slot = (pr + csl + 2 * nt) & 7;
                    uint2 b = *(const uint2*)&Bs[bnb + nt * 8 * LDB + 2 * slot];
                    hmma16816(acc[0][nt], a0[0], a0[1], a0[2], a0[3], b.x, b.y);
                    hmma16816(acc[1][nt], a1[0], a1[1], a1[2], a1[3], b.x, b.y);
                }
            }
        }

        // A(kcn) must have landed before the barrier
        asm volatile("cp.async.wait_group 0;" ::: "memory");

        // ---- stage B chunk kcn ----
        if (kcn < NKC) {
            uint32_t* Bn = sm + ((kcn & 1) ? OFF_B1 : OFF_B0);
            #pragma unroll
            for (int j = 0; j < 4; j++) {
                if (j < 3 || v3) {
                    const int c = kcn * KC + klr[j];
                    float4 s0 = *(const float4*)(sscf + 2 * c);
                    float4 s1 = *(const float4*)(sscf + 2 * (c + 8));
                    float h0 = fmaxf(fmaf(xv[j][0], s0.x, s0.y), 0.0f);
                    float h1 = fmaxf(fmaf(xv[j][1], s0.z, s0.w), 0.0f);
                    float h2 = fmaxf(fmaf(xv[j][2], s1.x, s1.y), 0.0f);
                    float h3 = fmaxf(fmaf(xv[j][3], s1.z, s1.w), 0.0f);
                    uint2 hb;
                    hb.x = pack_h2(h0, h1);
                    hb.y = pack_h2(h2, h3);
                    *(uint2*)(Bn + bsts[j]) = hb;
                }
            }
        }
        __syncthreads();
    }

    // ---- epilogue: acc -> SMEM payload -> coalesced vector STG ----
    float* P = (float*)sm;
    #pragma unroll
    for (int mt = 0; mt < 2; mt++) {
        const int rb = m0 + mt * 16 + g;
        #pragma unroll
        for (int nt = 0; nt < 7; nt++) {
            const int cb = n0 + nt * 8 + 2 * t;
            P[rb * PS + cb]           = acc[mt][nt][0];
            P[rb * PS + cb + 1]       = acc[mt][nt][1];
            P[(rb + 8) * PS + cb]     = acc[mt][nt][2];
            P[(rb + 8) * PS + cb + 1] = acc[mt][nt][3];
        }
    }
    __syncthreads();

    float* ob = out + (size_t)blockIdx.x * NB * COUT * HW;
    #pragma unroll
    for (int it = 0; it < 13; it++) {
        int f0 = (tid + it * 256) * 4;
        if (f0 < NB * COUT * HW) {
            float4 v;
            #pragma unroll
            for (int e = 0; e < 4; e++) {
                int f = f0 + e;
                int b = (f >= COUT * HW) ? 1 : 0;
                int r = f - b * (COUT * HW);
                int o = r / HW;
                int s = r - o * HW;
                ((float*)&v)[e] = P[o * PS + b * HW + s];
            }
            *(float4*)(ob + f0) = v;
        }
    }
}

extern "C" void kernel_launch(void* const* d_in, const int* in_sizes, int n_in,
                              void* d_out, int out_size)
{
    const float* x     = (const float*)d_in[0];
    const float* gamma = (const float*)d_in[1];
    const float* beta  = (const float*)d_in[2];
    const float* rmean = (const float*)d_in[3];
    const float* rvar  = (const float*)d_in[4];
    const float* W     = (const float*)d_in[5];
    float* out = (float*)d_out;

    w_cvt_kernel<<<84, 256>>>(W);
    cudaFuncSetAttribute(bn_conv_f16c,
                         cudaFuncAttributeMaxDynamicSharedMemorySize, SMEM_BYTES);
    bn_conv_f16c<<<GRID, 256, SMEM_BYTES>>>(x, gamma, beta, rmean, rvar, out);
}

// round 10
// speedup vs baseline: 1.4549x; 1.0122x over previous
#include <cuda_runtime.h>
#include <cuda_fp16.h>
#include <cstdint>

#define CIN   672
#define COUT  128
#define HW    49
#define NB    2
#define NREAL 98          // NB*HW
#define NPAD  112
#define KC    32          // sub-chunk K
#define NSUP  11          // super-chunks of K=64 (last has 1 sub)
#define GRID  512

#define LDA 20            // A row stride (half2 words): conflict-free frag reads
#define LDB 24            // B row stride (half2 words)
#define A_WORDS (COUT*LDA)   // 2560
#define B_WORDS (NPAD*LDB)   // 2688

#define OFF_SS 0                         // float2[672] = 1344 words
#define OFF_A0 1344                      // 4 A regions
#define OFF_B0 (OFF_A0 + 4*A_WORDS)      // 11584, 4 B regions
#define PIPE_WORDS (OFF_B0 + 4*B_WORDS)  // 22336 words
#define PS 113
#define P_WORDS (COUT*PS)                // 14464 < PIPE_WORDS
#define SMEM_BYTES (PIPE_WORDS*4)        // 89344 B -> 2 CTAs/SM (178.7KB)

// ---- fp16 copy of W, produced once by K0 ----
__device__ __align__(16) __half W16_buf[COUT * CIN];

__global__ void w_cvt_kernel(const float* __restrict__ W) {
    int i = blockIdx.x * 256 + threadIdx.x;      // 84*256 = 21504 = 86016/4
    float4 v = *(const float4*)(W + i * 4);
    __half2 h0 = __floats2half2_rn(v.x, v.y);
    __half2 h1 = __floats2half2_rn(v.z, v.w);
    uint2 q;
    q.x = *(uint32_t*)&h0;
    q.y = *(uint32_t*)&h1;
    *(uint2*)(W16_buf + i * 4) = q;
}

__device__ __forceinline__ void hmma16816(float c[4],
    uint32_t a0, uint32_t a1, uint32_t a2, uint32_t a3, uint32_t b0, uint32_t b1)
{
    asm volatile(
        "mma.sync.aligned.m16n8k16.row.col.f32.f16.f16.f32 "
        "{%0,%1,%2,%3}, {%4,%5,%6,%7}, {%8,%9}, {%0,%1,%2,%3};"
        : "+f"(c[0]), "+f"(c[1]), "+f"(c[2]), "+f"(c[3])
        : "r"(a0), "r"(a1), "r"(a2), "r"(a3), "r"(b0), "r"(b1));
}
__device__ __forceinline__ uint32_t pack_h2(float lo, float hi) {
    __half2 h = __floats2half2_rn(lo, hi);
    return *reinterpret_cast<uint32_t*>(&h);
}
__device__ __forceinline__ uint32_t smem_u32(const void* p) {
    uint32_t a;
    asm("{ .reg .u64 t; cvta.to.shared.u64 t, %1; cvt.u32.u64 %0, t; }" : "=r"(a) : "l"(p));
    return a;
}
__device__ __forceinline__ void cp16(uint32_t dst, const void* src) {
    asm volatile("cp.async.cg.shared.global [%0], [%1], 16;" :: "r"(dst), "l"(src) : "memory");
}

extern __shared__ uint32_t sm[];

__global__ void __launch_bounds__(256, 2)
bn_conv_sc(const float* __restrict__ x,
           const float* __restrict__ gamma,
           const float* __restrict__ beta,
           const float* __restrict__ rmean,
           const float* __restrict__ rvar,
           float* __restrict__ out)
{
    const int tid  = threadIdx.x;
    const int wid  = tid >> 5;
    const int lane = tid & 31;
    const int g = lane >> 2, t = lane & 3;
    const int m0 = (wid & 3) * 32;        // 4 warps over M=128
    const int n0 = (wid >> 2) * 56;       // 2 warps over N=112
    const uint32_t sb = smem_u32(sm);

    float2* ssc = (float2*)(sm + OFF_SS);
    const float* sscf = (const float*)ssc;

    // ---- prologue: BN fold + zero all 4 B regions ----
    for (int c = tid; c < CIN; c += 256) {
        float inv = rsqrtf(rvar[c] + 1e-5f);
        float s = gamma[c] * inv;
        ssc[c] = make_float2(s, beta[c] - rmean[c] * s);
    }
    for (int i = tid; i < 4 * B_WORDS; i += 256) sm[OFF_B0 + i] = 0u;

    // ---- per-thread staging constants (identical to R9) ----
    int xoff[4], bsts[4], klr[4];
    #pragma unroll
    for (int j = 0; j < 4; j++) {
        int i = tid + j * 256;
        if (i > 783) i = 783;
        int p = i / 98;
        int n = i - 98 * p;
        int tp = p & 3, ks = p >> 2;
        int kl = ks * 16 + tp * 2;
        int b = (n >= HW) ? 1 : 0;
        int s = n - HW * b;
        xoff[j] = (b * CIN + kl) * HW + s;
        bsts[j] = n * LDB + 2 * ((p + ((n >> 2) & 7)) & 7);   // conflict-free STS swizzle
        klr[j]  = kl;
    }
    const bool v3 = (tid < 16);

    // A cp.async: 512 quads per sub-chunk = 128 m x 4 q, 2 per thread
    const __half* a_src[2];
    uint32_t a_db[2];                 // byte offset within an A region
    #pragma unroll
    for (int i = 0; i < 2; i++) {
        int ia = tid + i * 256;
        int m = ia >> 2, q = ia & 3;
        a_src[i] = W16_buf + m * CIN + q * 8;
        a_db[i]  = (m * LDA + q * 4) * 4;
    }

    const float* xb = x + (size_t)blockIdx.x * NB * CIN * HW;
    __syncthreads();

    float acc[2][7][4];
    #pragma unroll
    for (int mt = 0; mt < 2; mt++)
        #pragma unroll
        for (int nt = 0; nt < 7; nt++)
            #pragma unroll
            for (int i = 0; i < 4; i++) acc[mt][nt][i] = 0.0f;

    const int ar00 = (m0 + g) * LDA;
    const int ar01 = (m0 + g + 8) * LDA;
    const int ar10 = (m0 + 16 + g) * LDA;
    const int ar11 = (m0 + 24 + g) * LDA;
    const int bnb  = (n0 + g) * LDB;
    const int csl  = (n0 >> 2) + (g >> 2);

    float xv[4][4];

    #pragma unroll 1
    for (int sc = -1; sc < NSUP; sc++) {
        const int scn = sc + 1;
        const int subs_n = (scn == NSUP - 1) ? 1 : 2;   // subs in super scn
        const int subs_c = (sc  == NSUP - 1) ? 1 : 2;   // subs in super sc

        // ---- cp.async A for super scn (all its subs) ----
        if (scn < NSUP) {
            #pragma unroll
            for (int sub = 0; sub < 2; sub++) {
                if (sub < subs_n) {
                    const int kcn = scn * 2 + sub;
                    const int r = (scn & 1) * 2 + sub;
                    const uint32_t abase = sb + (OFF_A0 + r * A_WORDS) * 4;
                    #pragma unroll
                    for (int i = 0; i < 2; i++)
                        cp16(abase + a_db[i], a_src[i] + kcn * KC);
                }
            }
            asm volatile("cp.async.commit_group;" ::: "memory");
        }

        // ---- two sub-chunk passes inside one barrier window ----
        #pragma unroll
        for (int sub = 0; sub < 2; sub++) {
            const bool stg = (scn < NSUP) && (sub < subs_n);
            const bool mma = (sc >= 0) && (sub < subs_c);

            // x LDGs for chunk scn*2+sub
            if (stg) {
                const int xadd = (scn * 2 + sub) * (KC * HW);
                #pragma unroll
                for (int j = 0; j < 4; j++) {
                    if (j < 3 || v3) {
                        const float* px = xb + xoff[j] + xadd;
                        xv[j][0] = px[0];
                        xv[j][1] = px[HW];
                        xv[j][2] = px[8 * HW];
                        xv[j][3] = px[9 * HW];
                    }
                }
            }

            // MMA on chunk sc*2+sub
            if (mma) {
                const int r = (sc & 1) * 2 + sub;
                const uint32_t* As = sm + OFF_A0 + r * A_WORDS;
                const uint32_t* Bs = sm + OFF_B0 + r * B_WORDS;
                #pragma unroll
                for (int ks = 0; ks < 2; ks++) {
                    const int ka = ks * 8 + t;
                    uint32_t a0[4], a1[4];
                    a0[0] = As[ar00 + ka];     a0[1] = As[ar01 + ka];
                    a0[2] = As[ar00 + ka + 4]; a0[3] = As[ar01 + ka + 4];
                    a1[0] = As[ar10 + ka];     a1[1] = As[ar11 + ka];
                    a1[2] = As[ar10 + ka + 4]; a1[3] = As[ar11 + ka + 4];
                    const int pr = ks * 4 + t;
                    #pragma unroll
                    for (int nt = 0; nt < 7; nt++) {
                        const int slot = (pr + csl + 2 * nt) & 7;
                        uint2 b = *(const uint2*)&Bs[bnb + nt * 8 * LDB + 2 * slot];
                        hmma16816(acc[0][nt], a0[0], a0[1], a0[2], a0[3], b.x, b.y);
                        hmma16816(acc[1][nt], a1[0], a1[1], a1[2], a1[3], b.x, b.y);
                    }
                }
            }

            // BN + ReLU + cvt + STS chunk scn*2+sub
            if (stg) {
                const int r = (scn & 1) * 2 + sub;
                uint32_t* Bn = sm + OFF_B0 + r * B_WORDS;
                const int kcb = (scn * 2 + sub) * KC;
                #pragma unroll
                for (int j = 0; j < 4; j++) {
                    if (j < 3 || v3) {
                        const int c = kcb + klr[j];
                        float4 s0 = *(const float4*)(sscf + 2 * c);
                        float4 s1 = *(const float4*)(sscf + 2 * (c + 8));
                        float h0 = fmaxf(fmaf(xv[j][0], s0.x, s0.y), 0.0f);
                        float h1 = fmaxf(fmaf(xv[j][1], s0.z, s0.w), 0.0f);
                        float h2 = fmaxf(fmaf(xv[j][2], s1.x, s1.y), 0.0f);
                        float h3 = fmaxf(fmaf(xv[j][3], s1.z, s1.w), 0.0f);
                        uint2 hb;
                        hb.x = pack_h2(h0, h1);
                        hb.y = pack_h2(h2, h3);
                        *(uint2*)(Bn + bsts[j]) = hb;
                    }
                }
            }
        }

        // A(scn) must have landed before the barrier releases consumers
        asm volatile("cp.async.wait_group 0;" ::: "memory");
        __syncthreads();
    }

    // ---- epilogue: acc -> SMEM payload -> coalesced vector STG ----
    float* P = (float*)sm;
    #pragma unroll
    for (int mt = 0; mt < 2; mt++) {
        const int rb = m0 + mt * 16 + g;
        #pragma unroll
        for (int nt = 0; nt < 7; nt++) {
            const int cb = n0 + nt * 8 + 2 * t;
            P[rb * PS + cb]           = acc[mt][nt][0];
            P[rb * PS + cb + 1]       = acc[mt][nt][1];
            P[(rb + 8) * PS + cb]     = acc[mt][nt][2];
            P[(rb + 8) * PS + cb + 1] = acc[mt][nt][3];
        }
    }
    __syncthreads();

    float* ob = out + (size_t)blockIdx.x * NB * COUT * HW;
    #pragma unroll
    for (int it = 0; it < 13; it++) {
        int f0 = (tid + it * 256) * 4;
        if (f0 < NB * COUT * HW) {
            float4 v;
            #pragma unroll
            for (int e = 0; e < 4; e++) {
                int f = f0 + e;
                int b = (f >= COUT * HW) ? 1 : 0;
                int r = f - b * (COUT * HW);
                int o = r / HW;
                int s = r - o * HW;
                ((float*)&v)[e] = P[o * PS + b * HW + s];
            }
            *(float4*)(ob + f0) = v;
        }
    }
}

extern "C" void kernel_launch(void* const* d_in, const int* in_sizes, int n_in,
                              void* d_out, int out_size)
{
    const float* x     = (const float*)d_in[0];
    const float* gamma = (const float*)d_in[1];
    const float* beta  = (const float*)d_in[2];
    const float* rmean = (const float*)d_in[3];
    const float* rvar  = (const float*)d_in[4];
    const float* W     = (const float*)d_in[5];
    float* out = (float*)d_out;

    w_cvt_kernel<<<84, 256>>>(W);
    cudaFuncSetAttribute(bn_conv_sc,
                         cudaFuncAttributeMaxDynamicSharedMemorySize, SMEM_BYTES);
    bn_conv_sc<<<GRID, 256, SMEM_BYTES>>>(x, gamma, beta, rmean, rvar, out);
}